// round 5
// baseline (speedup 1.0000x reference)
#include <cuda_runtime.h>

// Problem constants
#define Bv 4096
#define Dv 256
#define Rv 8
#define Kv 10
#define DL 10          // low dim
#define NC 100         // K*DL columns per replicate
#define INV_T 10.0f    // 1/TEMP, TEMP=0.1

// Scratch (device globals; no allocation allowed)
__device__ float g_xT[Dv * Bv];              // 4 MB transposed x: xT[D][b]
__device__ float g_G[Rv * Kv * DL * DL];     // 32 KB Gram matrices G[r][k][i][j]

typedef unsigned long long ull;

__device__ __forceinline__ ull pack2(float x, float y) {
    ull r; asm("mov.b64 %0, {%1, %2};" : "=l"(r) : "f"(x), "f"(y)); return r;
}
__device__ __forceinline__ void unpack2(ull v, float& x, float& y) {
    asm("mov.b64 {%0, %1}, %2;" : "=f"(x), "=f"(y) : "l"(v));
}
// d = a*b + d  (packed 2x fp32 FMA — 2x fp32 throughput on sm_103a)
__device__ __forceinline__ void fma2(ull& d, ull a, ull b) {
    asm("fma.rn.f32x2 %0, %1, %2, %0;" : "+l"(d) : "l"(a), "l"(b));
}
__device__ __forceinline__ void mul2(ull& d, ull a) {
    asm("mul.rn.f32x2 %0, %0, %1;" : "+l"(d) : "l"(a));
}

// ---------------------------------------------------------------------------
// Kernel 1: transpose x[b][D] -> g_xT[D][b]
// ---------------------------------------------------------------------------
__global__ void transpose_kernel(const float* __restrict__ x) {
    __shared__ float tile[32][33];
    int bx = blockIdx.x * 32;   // batch base
    int dx = blockIdx.y * 32;   // D base
    int tx = threadIdx.x, ty = threadIdx.y;  // (32, 8)
    #pragma unroll
    for (int i = ty; i < 32; i += 8)
        tile[i][tx] = x[(size_t)(bx + i) * Dv + dx + tx];   // tile[b'][d'] ; coalesced read
    __syncthreads();
    #pragma unroll
    for (int i = ty; i < 32; i += 8)
        g_xT[(size_t)(dx + i) * Bv + bx + tx] = tile[tx][i]; // coalesced write
}

// ---------------------------------------------------------------------------
// Kernel 2: G[r][k] = U^T U  (10x10 per (r,k), 80 blocks)
// ---------------------------------------------------------------------------
__global__ void g_kernel(const float* __restrict__ Us) {
    __shared__ float u[Dv * DL];  // 2560 floats, one U_rk tile
    int rk = blockIdx.x;          // 0..79
    const float* U = Us + (size_t)rk * Dv * DL;
    for (int i = threadIdx.x; i < Dv * DL; i += blockDim.x) u[i] = U[i];
    __syncthreads();
    int t = threadIdx.x;
    if (t < DL * DL) {
        int i = t / DL, j = t - (t / DL) * DL;
        float s = 0.0f;
        #pragma unroll 8
        for (int Dd = 0; Dd < Dv; ++Dd) s += u[Dd * DL + i] * u[Dd * DL + j];
        g_G[rk * (DL * DL) + t] = s;
    }
}

// ---------------------------------------------------------------------------
// Kernel 3: fused z -> softmax -> out, one block per (r, 256-batch tile)
//   smem: U_s[256][100] (102400B) | G_s[1000] (4000B) | stage[256*65] (66560B)
// ---------------------------------------------------------------------------
#define SMEM_FLOATS (Dv * NC + Kv * DL * DL + 256 * 65)

__global__ void __launch_bounds__(256, 1)
main_kernel(const float* __restrict__ Us, float* __restrict__ out) {
    extern __shared__ float sm[];
    float* U_s   = sm;                          // [D][kd]  (row = 100 floats = 400B, 16B-aligned)
    float* G_s   = sm + Dv * NC;                // [k][i][j]
    float* stage = sm + Dv * NC + Kv * DL * DL; // [tid][65] padded

    const int tid   = threadIdx.x;
    const int r     = blockIdx.y;
    const int bBase = blockIdx.x * 256;
    const int b     = bBase + tid;

    // Stage U_r into smem as U_s[D*100 + k*10 + d]
    const float* Ur = Us + (size_t)r * Kv * Dv * DL;
    for (int idx = tid; idx < Dv * NC; idx += 256) {
        int Dd  = idx / NC;
        int col = idx - Dd * NC;
        int k   = col / DL;
        int dd  = col - k * DL;
        U_s[idx] = Ur[(size_t)k * (Dv * DL) + Dd * DL + dd];
    }
    for (int idx = tid; idx < Kv * DL * DL; idx += 256)
        G_s[idx] = g_G[r * (Kv * DL * DL) + idx];
    __syncthreads();

    // ---- Phase 1: z[kd] = sum_D x[b][D] * U_s[D][kd]  (50 packed accumulators) ----
    ull z2[NC / 2];
    #pragma unroll
    for (int p = 0; p < NC / 2; ++p) z2[p] = 0ull;

    float xv = g_xT[b];
    for (int Dd = 0; Dd < Dv; ++Dd) {
        float xnext = (Dd + 1 < Dv) ? g_xT[(size_t)(Dd + 1) * Bv + b] : 0.0f;
        ull xp = pack2(xv, xv);
        const ull* Urow = (const ull*)(U_s + Dd * NC);   // 8B-aligned (400B row stride)
        #pragma unroll
        for (int p = 0; p < NC / 2; ++p) fma2(z2[p], xp, Urow[p]);
        xv = xnext;
    }

    // ---- Softmax over k: logit_k = (||z_k||^2 - 0.5 z_k G_k z_k^T) / T ----
    float logit[Kv];
    #pragma unroll
    for (int k = 0; k < Kv; ++k) {
        float zk[DL];
        #pragma unroll
        for (int p = 0; p < DL / 2; ++p) unpack2(z2[k * (DL / 2) + p], zk[2 * p], zk[2 * p + 1]);
        float nz = 0.0f;
        #pragma unroll
        for (int i = 0; i < DL; ++i) nz += zk[i] * zk[i];
        float q = 0.0f;
        #pragma unroll
        for (int i = 0; i < DL; ++i) {
            const float* Grow = G_s + k * (DL * DL) + i * DL;
            float t = 0.0f;
            #pragma unroll
            for (int j = 0; j < DL; ++j) t += Grow[j] * zk[j];
            q += zk[i] * t;
        }
        logit[k] = (nz - 0.5f * q) * INV_T;
    }
    float mx = logit[0];
    #pragma unroll
    for (int k = 1; k < Kv; ++k) mx = fmaxf(mx, logit[k]);
    float e[Kv], se = 0.0f;
    #pragma unroll
    for (int k = 0; k < Kv; ++k) { e[k] = expf(logit[k] - mx); se += e[k]; }
    float inv = 1.0f / se;
    #pragma unroll
    for (int k = 0; k < Kv; ++k) {
        float ck = e[k] * inv;
        ull ck2 = pack2(ck, ck);
        #pragma unroll
        for (int p = 0; p < DL / 2; ++p) mul2(z2[k * (DL / 2) + p], ck2);
    }

    // ---- Phase 2: out[r][b][D] = sum_kd w[kd] * U_s[D][kd], staged for coalescing ----
    float* outr = out + (size_t)r * Bv * Dv;
    for (int Dc = 0; Dc < Dv; Dc += 64) {
        #pragma unroll 2
        for (int j = 0; j < 64; ++j) {
            int Dd = Dc + j;
            ull acc = 0ull;
            const ull* Urow = (const ull*)(U_s + Dd * NC);
            #pragma unroll
            for (int p = 0; p < NC / 2; ++p) fma2(acc, z2[p], Urow[p]);
            float lo, hi; unpack2(acc, lo, hi);
            stage[tid * 65 + j] = lo + hi;   // stride 65: conflict-free
        }
        __syncthreads();
        for (int t = tid; t < 256 * 64; t += 256) {
            int i = t >> 6;
            int j = t & 63;
            outr[(size_t)(bBase + i) * Dv + Dc + j] = stage[i * 65 + j];  // coalesced
        }
        __syncthreads();
    }
}

// ---------------------------------------------------------------------------
extern "C" void kernel_launch(void* const* d_in, const int* in_sizes, int n_in,
                              void* d_out, int out_size) {
    const float* x  = (const float*)d_in[0];   // (B, D) fp32
    const float* Us = (const float*)d_in[1];   // (R, K, D, DL) fp32
    float* out = (float*)d_out;                // (R, B, D) fp32

    cudaFuncSetAttribute(main_kernel, cudaFuncAttributeMaxDynamicSharedMemorySize,
                         SMEM_FLOATS * (int)sizeof(float));

    transpose_kernel<<<dim3(Bv / 32, Dv / 32), dim3(32, 8)>>>(x);
    g_kernel<<<Rv * Kv, 128>>>(Us);
    main_kernel<<<dim3(Bv / 256, Rv), 256, SMEM_FLOATS * (int)sizeof(float)>>>(Us, out);
}